// round 8
// baseline (speedup 1.0000x reference)
#include <cuda_runtime.h>
#include <math.h>

#define BB 8
#define HH 32
#define DD 128
#define NLL 1
#define NCTA 296      // 148 SMs * 2 CTAs, one wave at occupancy 2
#define MAXSLOT 64

// Scratch (device allocs forbidden)
__device__ __align__(16) float g_po[(size_t)BB * MAXSLOT * HH * DD];
__device__ float g_pm[BB * MAXSLOT * HH];
__device__ float g_pl[BB * MAXSLOT * HH];
__device__ int   g_cnt[BB];        // zero-init; self-resetting per batch

__device__ __forceinline__ int cta_of(long long p, long long base, long long rem) {
    long long thr = rem * (base + 1);
    if (p < thr) return (int)(p / (base + 1));
    return (int)(rem + (p - thr) / base);
}

// One CTA = all 32 heads of one batch over a position range.
// Warp w -> heads 4w..4w+3. Last CTA per batch also does the combine.
__global__ __launch_bounds__(256, 2) void attn_batch_k(
    const float* __restrict__ qkv,
    const float* __restrict__ kc,
    const float* __restrict__ vc,
    const int* __restrict__ plen,
    const int* __restrict__ playr,
    float* __restrict__ out,
    int Scap)
{
    __shared__ float s_cos[DD / 2], s_sin[DD / 2];
    __shared__ float s_m[MAXSLOT][HH];
    __shared__ float s_l[MAXSLOT][HH];
    __shared__ int   s_last;

    const int n = *plen;
    const int Lidx = *playr;
    const int nm = n - 1;                      // streamed positions per batch
    const long long P = (long long)BB * nm;
    const long long base = P / NCTA;
    const long long rem  = P - base * NCTA;

    const int cta = blockIdx.x;
    const long long start = (long long)cta * base + min((long long)cta, rem);
    const long long end   = start + base + ((long long)cta < rem ? 1 : 0);

    const int tid  = threadIdx.x;
    const int warp = tid >> 5;
    const int lane = tid & 31;
    const int h0   = warp * 4;
    const float scale = rsqrtf((float)DD);

    if (tid < DD / 2) {
        float inv = powf(10000.0f, -(float)(2 * tid) / (float)DD);
        float fr = (float)(n - 1) * inv;
        sincosf(fr, &s_sin[tid], &s_cos[tid]);
    }
    __syncthreads();

    // thread's float4 covers dims [lane*4, lane*4+4) -> rope pairs lane*2, lane*2+1
    const float c0 = s_cos[lane * 2],     sn0 = s_sin[lane * 2];
    const float c1 = s_cos[lane * 2 + 1], sn1 = s_sin[lane * 2 + 1];

    const int b0 = (int)(start / nm);
    const int b1 = (int)((end - 1) / nm);

    for (int b = b0; b <= b1; b++) {
        const int a = (int)(max(start, (long long)b * nm) - (long long)b * nm);
        const int e = (int)(min(end, (long long)(b + 1) * nm) - (long long)b * nm);
        const bool last_owner = (e == nm);

        // roped q for this warp's 4 heads
        float4 q[4];
        #pragma unroll
        for (int i = 0; i < 4; i++) {
            float4 x = *((const float4*)(qkv + ((size_t)(b * 3 + 0) * HH + h0 + i) * DD) + lane);
            q[i].x = x.x * c0 - x.y * sn0;
            q[i].y = x.y * c0 + x.x * sn0;
            q[i].z = x.z * c1 - x.w * sn1;
            q[i].w = x.w * c1 + x.z * sn1;
        }

        const float4* kr = (const float4*)(kc + ((size_t)(b * NLL + Lidx) * Scap) * HH * DD)
                           + (size_t)a * (HH * DD / 4) + h0 * (DD / 4) + lane;
        const float4* vr = (const float4*)(vc + ((size_t)(b * NLL + Lidx) * Scap) * HH * DD)
                           + (size_t)a * (HH * DD / 4) + h0 * (DD / 4) + lane;

        float  m[4] = {-INFINITY, -INFINITY, -INFINITY, -INFINITY};
        float  l[4] = {0.f, 0.f, 0.f, 0.f};
        float4 acc[4];
        #pragma unroll
        for (int i = 0; i < 4; i++) acc[i] = make_float4(0.f, 0.f, 0.f, 0.f);

        float4 KA[4], VA[4], KB[4], VB[4];

#define LOADN(KX, VX) do {                                                    \
            KX[0] = __ldcs(kr);      KX[1] = __ldcs(kr + 32);                 \
            KX[2] = __ldcs(kr + 64); KX[3] = __ldcs(kr + 96);                 \
            VX[0] = __ldcs(vr);      VX[1] = __ldcs(vr + 32);                 \
            VX[2] = __ldcs(vr + 64); VX[3] = __ldcs(vr + 96);                 \
            kr += (HH * DD / 4); vr += (HH * DD / 4);                         \
        } while (0)

#define STEP(KX, VX) do {                                                     \
            float dd[4];                                                      \
            _Pragma("unroll")                                                 \
            for (int i = 0; i < 4; i++)                                       \
                dd[i] = q[i].x * KX[i].x + q[i].y * KX[i].y                   \
                      + q[i].z * KX[i].z + q[i].w * KX[i].w;                  \
            _Pragma("unroll")                                                 \
            for (int off = 16; off; off >>= 1) {                              \
                dd[0] += __shfl_xor_sync(0xffffffffu, dd[0], off);            \
                dd[1] += __shfl_xor_sync(0xffffffffu, dd[1], off);            \
                dd[2] += __shfl_xor_sync(0xffffffffu, dd[2], off);            \
                dd[3] += __shfl_xor_sync(0xffffffffu, dd[3], off);            \
            }                                                                 \
            _Pragma("unroll")                                                 \
            for (int i = 0; i < 4; i++) {                                     \
                float d = dd[i] * scale;                                      \
                float mn = fmaxf(m[i], d);                                    \
                float corr = __expf(m[i] - mn);                               \
                float w = __expf(d - mn);                                     \
                l[i] = l[i] * corr + w;                                       \
                acc[i].x = acc[i].x * corr + w * VX[i].x;                     \
                acc[i].y = acc[i].y * corr + w * VX[i].y;                     \
                acc[i].z = acc[i].z * corr + w * VX[i].z;                     \
                acc[i].w = acc[i].w * corr + w * VX[i].w;                     \
                m[i] = mn;                                                    \
            }                                                                 \
        } while (0)

        if (a < e) {
            LOADN(KA, VA);                 // pos a
            int s = a;
            for (; s + 1 < e; s += 2) {
                LOADN(KB, VB);             // pos s+1
                STEP(KA, VA);              // compute pos s
                if (s + 2 < e) LOADN(KA, VA);
                STEP(KB, VB);              // compute pos s+1
            }
            if (s < e) STEP(KA, VA);       // odd tail
        }

        // new position n-1: roped k + v straight from qkv
        if (last_owner) {
            float4 kk[4], vv[4];
            #pragma unroll
            for (int i = 0; i < 4; i++) {
                float4 x = *((const float4*)(qkv + ((size_t)(b * 3 + 1) * HH + h0 + i) * DD) + lane);
                kk[i].x = x.x * c0 - x.y * sn0;
                kk[i].y = x.y * c0 + x.x * sn0;
                kk[i].z = x.z * c1 - x.w * sn1;
                kk[i].w = x.w * c1 + x.z * sn1;
                vv[i] = *((const float4*)(qkv + ((size_t)(b * 3 + 2) * HH + h0 + i) * DD) + lane);
            }
            STEP(kk, vv);
        }
#undef LOADN
#undef STEP

        // ---- write partials ----
        const int cfirst = cta_of((long long)b * nm, base, rem);
        const int clast  = cta_of((long long)(b + 1) * nm - 1, base, rem);
        const int ns = clast - cfirst + 1;
        const int slot = cta - cfirst;

        #pragma unroll
        for (int i = 0; i < 4; i++)
            *((float4*)(g_po + (((size_t)b * MAXSLOT + slot) * HH + h0 + i) * DD) + lane) = acc[i];
        if (lane < 4) {
            float mv = lane == 0 ? m[0] : lane == 1 ? m[1] : lane == 2 ? m[2] : m[3];
            float lv = lane == 0 ? l[0] : lane == 1 ? l[1] : lane == 2 ? l[2] : l[3];
            g_pm[((size_t)b * MAXSLOT + slot) * HH + h0 + lane] = mv;
            g_pl[((size_t)b * MAXSLOT + slot) * HH + h0 + lane] = lv;
        }
        __threadfence();
        __syncthreads();

        if (tid == 0) {
            int old = atomicAdd(&g_cnt[b], 1);
            int last = (old == ns - 1);
            if (last) g_cnt[b] = 0;        // reset for next graph replay
            s_last = last;
        }
        __syncthreads();

        // ---- last CTA of batch b combines all its partials ----
        if (s_last) {
            __threadfence();
            // stage m/l into smem (coalesced: consecutive tid -> consecutive h,s)
            for (int i = tid; i < ns * HH; i += 256) {
                s_m[i >> 5][i & 31] = g_pm[(size_t)b * MAXSLOT * HH + i];
                s_l[i >> 5][i & 31] = g_pl[(size_t)b * MAXSLOT * HH + i];
            }
            __syncthreads();

            // warp w handles heads w, w+8, w+16, w+24
            #pragma unroll
            for (int hi = 0; hi < 4; hi++) {
                const int h = warp + hi * 8;
                float M = -INFINITY;
                for (int s = 0; s < ns; s++) M = fmaxf(M, s_m[s][h]);
                float Lt = 0.f;
                float4 o = make_float4(0.f, 0.f, 0.f, 0.f);
                const float4* pp = (const float4*)(g_po + ((size_t)b * MAXSLOT * HH + h) * DD) + lane;
                for (int s = 0; s < ns; s++) {
                    float ee = __expf(s_m[s][h] - M);
                    Lt += ee * s_l[s][h];
                    float4 v = pp[(size_t)s * (HH * DD / 4)];
                    o.x += ee * v.x; o.y += ee * v.y;
                    o.z += ee * v.z; o.w += ee * v.w;
                }
                float inv = 1.0f / Lt;
                float4 r = make_float4(o.x * inv, o.y * inv, o.z * inv, o.w * inv);
                *((float4*)(out + ((size_t)b * HH + h) * DD) + lane) = r;
            }
            __syncthreads();
        }
    }
}

extern "C" void kernel_launch(void* const* d_in, const int* in_sizes, int n_in,
                              void* d_out, int out_size) {
    const float* qkv = (const float*)d_in[0];
    const float* kc  = (const float*)d_in[1];
    const float* vc  = (const float*)d_in[2];
    const int* plen  = (const int*)d_in[3];
    const int* playr = (const int*)d_in[4];
    float* out = (float*)d_out;

    int Scap = in_sizes[1] / (BB * NLL * HH * DD);

    attn_batch_k<<<NCTA, 256>>>(qkv, kc, vc, plen, playr, out, Scap);
}

// round 9
// speedup vs baseline: 1.0943x; 1.0943x over previous
#include <cuda_runtime.h>
#include <math.h>

#define BB 8
#define HH 32
#define DD 128
#define NLL 1
#define NCTA 296      // 148 SMs * 2 CTAs, one wave at occupancy 2
#define MAXSLOT 64

// Scratch (device allocs forbidden)
__device__ __align__(16) float g_po[(size_t)BB * MAXSLOT * HH * DD];
__device__ float g_pm[BB * MAXSLOT * HH];
__device__ float g_pl[BB * MAXSLOT * HH];

__device__ __forceinline__ int cta_of(long long p, long long base, long long rem) {
    long long thr = rem * (base + 1);
    if (p < thr) return (int)(p / (base + 1));
    return (int)(rem + (p - thr) / base);
}

// One CTA = all 32 heads of one batch over a position range.
// Warp w -> heads 4w..4w+3. Load instr i = head 4w+i row, fully coalesced.
__global__ __launch_bounds__(256, 2) void attn_batch_k(
    const float* __restrict__ qkv,
    const float* __restrict__ kc,
    const float* __restrict__ vc,
    const int* __restrict__ plen,
    const int* __restrict__ playr,
    int Scap)
{
    __shared__ float s_cos[DD / 2], s_sin[DD / 2];

    const int n = *plen;
    const int Lidx = *playr;
    const int nm = n - 1;                      // streamed positions per batch
    const long long P = (long long)BB * nm;
    const long long base = P / NCTA;
    const long long rem  = P - base * NCTA;

    const int cta = blockIdx.x;
    const long long start = (long long)cta * base + min((long long)cta, rem);
    const long long end   = start + base + ((long long)cta < rem ? 1 : 0);

    const int tid  = threadIdx.x;
    const int warp = tid >> 5;
    const int lane = tid & 31;
    const int h0   = warp * 4;
    const float scale = rsqrtf((float)DD);

    if (tid < DD / 2) {
        float inv = powf(10000.0f, -(float)(2 * tid) / (float)DD);
        float fr = (float)(n - 1) * inv;
        sincosf(fr, &s_sin[tid], &s_cos[tid]);
    }
    __syncthreads();

    // thread's float4 covers dims [lane*4, lane*4+4) -> rope pairs lane*2, lane*2+1
    const float c0 = s_cos[lane * 2],     sn0 = s_sin[lane * 2];
    const float c1 = s_cos[lane * 2 + 1], sn1 = s_sin[lane * 2 + 1];

    const int b0 = (int)(start / nm);
    const int b1 = (int)((end - 1) / nm);

    for (int b = b0; b <= b1; b++) {
        const int a = (int)(max(start, (long long)b * nm) - (long long)b * nm);
        const int e = (int)(min(end, (long long)(b + 1) * nm) - (long long)b * nm);
        const bool last_owner = (e == nm);

        // roped q for this warp's 4 heads
        float4 q[4];
        #pragma unroll
        for (int i = 0; i < 4; i++) {
            float4 x = *((const float4*)(qkv + ((size_t)(b * 3 + 0) * HH + h0 + i) * DD) + lane);
            q[i].x = x.x * c0 - x.y * sn0;
            q[i].y = x.y * c0 + x.x * sn0;
            q[i].z = x.z * c1 - x.w * sn1;
            q[i].w = x.w * c1 + x.z * sn1;
        }

        const float4* kr = (const float4*)(kc + ((size_t)(b * NLL + Lidx) * Scap) * HH * DD)
                           + (size_t)a * (HH * DD / 4) + h0 * (DD / 4) + lane;
        const float4* vr = (const float4*)(vc + ((size_t)(b * NLL + Lidx) * Scap) * HH * DD)
                           + (size_t)a * (HH * DD / 4) + h0 * (DD / 4) + lane;

        float  m[4] = {-INFINITY, -INFINITY, -INFINITY, -INFINITY};
        float  l[4] = {0.f, 0.f, 0.f, 0.f};
        float4 acc[4];
        #pragma unroll
        for (int i = 0; i < 4; i++) acc[i] = make_float4(0.f, 0.f, 0.f, 0.f);

        float4 KA[4], VA[4], KB[4], VB[4];

#define LOADN(KX, VX) do {                                                    \
            KX[0] = __ldcs(kr);      KX[1] = __ldcs(kr + 32);                 \
            KX[2] = __ldcs(kr + 64); KX[3] = __ldcs(kr + 96);                 \
            VX[0] = __ldcs(vr);      VX[1] = __ldcs(vr + 32);                 \
            VX[2] = __ldcs(vr + 64); VX[3] = __ldcs(vr + 96);                 \
            kr += (HH * DD / 4); vr += (HH * DD / 4);                         \
        } while (0)

#define STEP(KX, VX) do {                                                     \
            float dd[4];                                                      \
            _Pragma("unroll")                                                 \
            for (int i = 0; i < 4; i++)                                       \
                dd[i] = q[i].x * KX[i].x + q[i].y * KX[i].y                   \
                      + q[i].z * KX[i].z + q[i].w * KX[i].w;                  \
            _Pragma("unroll")                                                 \
            for (int off = 16; off; off >>= 1) {                              \
                dd[0] += __shfl_xor_sync(0xffffffffu, dd[0], off);            \
                dd[1] += __shfl_xor_sync(0xffffffffu, dd[1], off);            \
                dd[2] += __shfl_xor_sync(0xffffffffu, dd[2], off);            \
                dd[3] += __shfl_xor_sync(0xffffffffu, dd[3], off);            \
            }                                                                 \
            _Pragma("unroll")                                                 \
            for (int i = 0; i < 4; i++) {                                     \
                float d = dd[i] * scale;                                      \
                float mn = fmaxf(m[i], d);                                    \
                float corr = __expf(m[i] - mn);                               \
                float w = __expf(d - mn);                                     \
                l[i] = l[i] * corr + w;                                       \
                acc[i].x = acc[i].x * corr + w * VX[i].x;                     \
                acc[i].y = acc[i].y * corr + w * VX[i].y;                     \
                acc[i].z = acc[i].z * corr + w * VX[i].z;                     \
                acc[i].w = acc[i].w * corr + w * VX[i].w;                     \
                m[i] = mn;                                                    \
            }                                                                 \
        } while (0)

        if (a < e) {
            LOADN(KA, VA);                 // pos a
            int s = a;
            for (; s + 1 < e; s += 2) {
                LOADN(KB, VB);             // pos s+1
                STEP(KA, VA);              // compute pos s
                if (s + 2 < e) LOADN(KA, VA);
                STEP(KB, VB);              // compute pos s+1
            }
            if (s < e) STEP(KA, VA);       // odd tail
        }

        // new position n-1: roped k + v straight from qkv
        if (last_owner) {
            float4 kk[4], vv[4];
            #pragma unroll
            for (int i = 0; i < 4; i++) {
                float4 x = *((const float4*)(qkv + ((size_t)(b * 3 + 1) * HH + h0 + i) * DD) + lane);
                kk[i].x = x.x * c0 - x.y * sn0;
                kk[i].y = x.y * c0 + x.x * sn0;
                kk[i].z = x.z * c1 - x.w * sn1;
                kk[i].w = x.w * c1 + x.z * sn1;
                vv[i] = *((const float4*)(qkv + ((size_t)(b * 3 + 2) * HH + h0 + i) * DD) + lane);
            }
            STEP(kk, vv);
        }
#undef LOADN
#undef STEP

        // write partials
        const int slot = cta - cta_of((long long)b * nm, base, rem);
        #pragma unroll
        for (int i = 0; i < 4; i++)
            *((float4*)(g_po + (((size_t)b * MAXSLOT + slot) * HH + h0 + i) * DD) + lane) = acc[i];
        if (lane < 4) {
            float mv = lane == 0 ? m[0] : lane == 1 ? m[1] : lane == 2 ? m[2] : m[3];
            float lv = lane == 0 ? l[0] : lane == 1 ? l[1] : lane == 2 ? l[2] : l[3];
            g_pm[((size_t)b * MAXSLOT + slot) * HH + h0 + lane] = mv;
            g_pl[((size_t)b * MAXSLOT + slot) * HH + h0 + lane] = lv;
        }
    }
}

// Combine: one block per (b,h), 256 threads = 8 warps.
// Warp w accumulates slots w, w+8, ... with one float4 per lane (512B/slot).
__global__ __launch_bounds__(256) void reduce4_k(
    float* __restrict__ out, const int* __restrict__ plen)
{
    __shared__ float sm[MAXSLOT], sl[MAXSLOT];
    __shared__ float4 pO[8][32];
    __shared__ float  pL[8];

    const int bh = blockIdx.x;
    const int b = bh >> 5, h = bh & 31;
    const int tid = threadIdx.x;
    const int warp = tid >> 5;
    const int lane = tid & 31;

    const int n = *plen;
    const int nm = n - 1;
    const long long P = (long long)BB * nm;
    const long long base = P / NCTA;
    const long long rem  = P - base * NCTA;

    const int cfirst = cta_of((long long)b * nm, base, rem);
    const int clast  = cta_of((long long)(b + 1) * nm - 1, base, rem);
    const int ns = clast - cfirst + 1;

    if (tid < ns) {
        sm[tid] = g_pm[((size_t)b * MAXSLOT + tid) * HH + h];
        sl[tid] = g_pl[((size_t)b * MAXSLOT + tid) * HH + h];
    }
    __syncthreads();

    float M = -INFINITY;
    for (int s = 0; s < ns; s++) M = fmaxf(M, sm[s]);

    float L = 0.f;
    float4 o = make_float4(0.f, 0.f, 0.f, 0.f);
    const float4* pp = (const float4*)(g_po + ((size_t)b * MAXSLOT * HH + h) * DD) + lane;
    for (int s = warp; s < ns; s += 8) {
        float e = __expf(sm[s] - M);
        L += e * sl[s];
        float4 v = pp[(size_t)s * (HH * DD / 4)];
        o.x += e * v.x; o.y += e * v.y; o.z += e * v.z; o.w += e * v.w;
    }
    pO[warp][lane] = o;
    if (lane == 0) pL[warp] = L;
    __syncthreads();

    if (warp == 0) {
        float Lt = 0.f;
        float4 ot = make_float4(0.f, 0.f, 0.f, 0.f);
        #pragma unroll
        for (int i = 0; i < 8; i++) {
            Lt += pL[i];
            float4 v = pO[i][lane];
            ot.x += v.x; ot.y += v.y; ot.z += v.z; ot.w += v.w;
        }
        float inv = 1.0f / Lt;
        float4 r = make_float4(ot.x * inv, ot.y * inv, ot.z * inv, ot.w * inv);
        *((float4*)(out + (size_t)bh * DD) + lane) = r;
    }
}

extern "C" void kernel_launch(void* const* d_in, const int* in_sizes, int n_in,
                              void* d_out, int out_size) {
    const float* qkv = (const float*)d_in[0];
    const float* kc  = (const float*)d_in[1];
    const float* vc  = (const float*)d_in[2];
    const int* plen  = (const int*)d_in[3];
    const int* playr = (const int*)d_in[4];
    float* out = (float*)d_out;

    int Scap = in_sizes[1] / (BB * NLL * HH * DD);

    attn_batch_k<<<NCTA, 256>>>(qkv, kc, vc, plen, playr, Scap);
    reduce4_k<<<BB * HH, 256>>>(out, plen);
}

// round 10
// speedup vs baseline: 1.1056x; 1.0103x over previous
#include <cuda_runtime.h>
#include <math.h>

#define BB 8
#define HH 32
#define DD 128
#define NLL 1
#define NCTA 296      // 148 SMs * 2 CTAs, one wave at occupancy 2
#define MAXSLOT 64
#define NPF 8         // max slots per warp in reducer (ns <= 64, 8 warps)

// Scratch (device allocs forbidden)
__device__ __align__(16) float g_po[(size_t)BB * MAXSLOT * HH * DD];
__device__ float g_pm[BB * MAXSLOT * HH];
__device__ float g_pl[BB * MAXSLOT * HH];

__device__ __forceinline__ int cta_of(long long p, long long base, long long rem) {
    long long thr = rem * (base + 1);
    if (p < thr) return (int)(p / (base + 1));
    return (int)(rem + (p - thr) / base);
}

// One CTA = all 32 heads of one batch over a position range.
// Warp w -> heads 4w..4w+3. Load instr i = head 4w+i row, fully coalesced.
__global__ __launch_bounds__(256, 2) void attn_batch_k(
    const float* __restrict__ qkv,
    const float* __restrict__ kc,
    const float* __restrict__ vc,
    const int* __restrict__ plen,
    const int* __restrict__ playr,
    int Scap)
{
    __shared__ float s_cos[DD / 2], s_sin[DD / 2];

    const int n = *plen;
    const int Lidx = *playr;
    const int nm = n - 1;                      // streamed positions per batch
    const long long P = (long long)BB * nm;
    const long long base = P / NCTA;
    const long long rem  = P - base * NCTA;

    const int cta = blockIdx.x;
    const long long start = (long long)cta * base + min((long long)cta, rem);
    const long long end   = start + base + ((long long)cta < rem ? 1 : 0);

    const int tid  = threadIdx.x;
    const int warp = tid >> 5;
    const int lane = tid & 31;
    const int h0   = warp * 4;
    const float scale = rsqrtf((float)DD);

    if (tid < DD / 2) {
        float inv = powf(10000.0f, -(float)(2 * tid) / (float)DD);
        float fr = (float)(n - 1) * inv;
        sincosf(fr, &s_sin[tid], &s_cos[tid]);
    }
    __syncthreads();

    // thread's float4 covers dims [lane*4, lane*4+4) -> rope pairs lane*2, lane*2+1
    const float c0 = s_cos[lane * 2],     sn0 = s_sin[lane * 2];
    const float c1 = s_cos[lane * 2 + 1], sn1 = s_sin[lane * 2 + 1];

    const int b0 = (int)(start / nm);
    const int b1 = (int)((end - 1) / nm);

    for (int b = b0; b <= b1; b++) {
        const int a = (int)(max(start, (long long)b * nm) - (long long)b * nm);
        const int e = (int)(min(end, (long long)(b + 1) * nm) - (long long)b * nm);
        const bool last_owner = (e == nm);

        // roped q for this warp's 4 heads
        float4 q[4];
        #pragma unroll
        for (int i = 0; i < 4; i++) {
            float4 x = *((const float4*)(qkv + ((size_t)(b * 3 + 0) * HH + h0 + i) * DD) + lane);
            q[i].x = x.x * c0 - x.y * sn0;
            q[i].y = x.y * c0 + x.x * sn0;
            q[i].z = x.z * c1 - x.w * sn1;
            q[i].w = x.w * c1 + x.z * sn1;
        }

        const float4* kr = (const float4*)(kc + ((size_t)(b * NLL + Lidx) * Scap) * HH * DD)
                           + (size_t)a * (HH * DD / 4) + h0 * (DD / 4) + lane;
        const float4* vr = (const float4*)(vc + ((size_t)(b * NLL + Lidx) * Scap) * HH * DD)
                           + (size_t)a * (HH * DD / 4) + h0 * (DD / 4) + lane;

        float  m[4] = {-INFINITY, -INFINITY, -INFINITY, -INFINITY};
        float  l[4] = {0.f, 0.f, 0.f, 0.f};
        float4 acc[4];
        #pragma unroll
        for (int i = 0; i < 4; i++) acc[i] = make_float4(0.f, 0.f, 0.f, 0.f);

        float4 KA[4], VA[4], KB[4], VB[4];

#define LOADN(KX, VX) do {                                                    \
            KX[0] = __ldcs(kr);      KX[1] = __ldcs(kr + 32);                 \
            KX[2] = __ldcs(kr + 64); KX[3] = __ldcs(kr + 96);                 \
            VX[0] = __ldcs(vr);      VX[1] = __ldcs(vr + 32);                 \
            VX[2] = __ldcs(vr + 64); VX[3] = __ldcs(vr + 96);                 \
            kr += (HH * DD / 4); vr += (HH * DD / 4);                         \
        } while (0)

#define STEP(KX, VX) do {                                                     \
            float dd[4];                                                      \
            _Pragma("unroll")                                                 \
            for (int i = 0; i < 4; i++)                                       \
                dd[i] = q[i].x * KX[i].x + q[i].y * KX[i].y                   \
                      + q[i].z * KX[i].z + q[i].w * KX[i].w;                  \
            _Pragma("unroll")                                                 \
            for (int off = 16; off; off >>= 1) {                              \
                dd[0] += __shfl_xor_sync(0xffffffffu, dd[0], off);            \
                dd[1] += __shfl_xor_sync(0xffffffffu, dd[1], off);            \
                dd[2] += __shfl_xor_sync(0xffffffffu, dd[2], off);            \
                dd[3] += __shfl_xor_sync(0xffffffffu, dd[3], off);            \
            }                                                                 \
            _Pragma("unroll")                                                 \
            for (int i = 0; i < 4; i++) {                                     \
                float d = dd[i] * scale;                                      \
                float mn = fmaxf(m[i], d);                                    \
                float corr = __expf(m[i] - mn);                               \
                float w = __expf(d - mn);                                     \
                l[i] = l[i] * corr + w;                                       \
                acc[i].x = acc[i].x * corr + w * VX[i].x;                     \
                acc[i].y = acc[i].y * corr + w * VX[i].y;                     \
                acc[i].z = acc[i].z * corr + w * VX[i].z;                     \
                acc[i].w = acc[i].w * corr + w * VX[i].w;                     \
                m[i] = mn;                                                    \
            }                                                                 \
        } while (0)

        if (a < e) {
            LOADN(KA, VA);                 // pos a
            int s = a;
            for (; s + 1 < e; s += 2) {
                LOADN(KB, VB);             // pos s+1
                STEP(KA, VA);              // compute pos s
                if (s + 2 < e) LOADN(KA, VA);
                STEP(KB, VB);              // compute pos s+1
            }
            if (s < e) STEP(KA, VA);       // odd tail
        }

        // new position n-1: roped k + v straight from qkv
        if (last_owner) {
            float4 kk[4], vv[4];
            #pragma unroll
            for (int i = 0; i < 4; i++) {
                float4 x = *((const float4*)(qkv + ((size_t)(b * 3 + 1) * HH + h0 + i) * DD) + lane);
                kk[i].x = x.x * c0 - x.y * sn0;
                kk[i].y = x.y * c0 + x.x * sn0;
                kk[i].z = x.z * c1 - x.w * sn1;
                kk[i].w = x.w * c1 + x.z * sn1;
                vv[i] = *((const float4*)(qkv + ((size_t)(b * 3 + 2) * HH + h0 + i) * DD) + lane);
            }
            STEP(kk, vv);
        }
#undef LOADN
#undef STEP

        // write partials
        const int slot = cta - cta_of((long long)b * nm, base, rem);
        #pragma unroll
        for (int i = 0; i < 4; i++)
            *((float4*)(g_po + (((size_t)b * MAXSLOT + slot) * HH + h0 + i) * DD) + lane) = acc[i];
        if (lane < 4) {
            float mv = lane == 0 ? m[0] : lane == 1 ? m[1] : lane == 2 ? m[2] : m[3];
            float lv = lane == 0 ? l[0] : lane == 1 ? l[1] : lane == 2 ? l[2] : l[3];
            g_pm[((size_t)b * MAXSLOT + slot) * HH + h0 + lane] = mv;
            g_pl[((size_t)b * MAXSLOT + slot) * HH + h0 + lane] = lv;
        }
    }
}

// Combine: one block per (b,h), 256 threads = 8 warps.
// Warp w handles slots w, w+8, ...: ALL loads prefetched (predicated, MLP=NPF)
// before any accumulation; M computed warp-parallel via shuffles.
__global__ __launch_bounds__(256) void reduce5_k(
    float* __restrict__ out, const int* __restrict__ plen)
{
    __shared__ float sm[MAXSLOT], sl[MAXSLOT];
    __shared__ float4 pO[8][32];
    __shared__ float  pL[8];

    const int bh = blockIdx.x;
    const int b = bh >> 5, h = bh & 31;
    const int tid = threadIdx.x;
    const int warp = tid >> 5;
    const int lane = tid & 31;

    const int n = *plen;
    const int nm = n - 1;
    const long long P = (long long)BB * nm;
    const long long base = P / NCTA;
    const long long rem  = P - base * NCTA;

    const int cfirst = cta_of((long long)b * nm, base, rem);
    const int clast  = cta_of((long long)(b + 1) * nm - 1, base, rem);
    const int ns = clast - cfirst + 1;

    if (tid < ns) {
        sm[tid] = g_pm[((size_t)b * MAXSLOT + tid) * HH + h];
        sl[tid] = g_pl[((size_t)b * MAXSLOT + tid) * HH + h];
    }
    __syncthreads();

    // warp-parallel max: lane-parallel reads + shuffle reduction
    float M = (lane < ns) ? sm[lane] : -INFINITY;
    if (lane + 32 < ns) M = fmaxf(M, sm[lane + 32]);
    #pragma unroll
    for (int off = 16; off; off >>= 1)
        M = fmaxf(M, __shfl_xor_sync(0xffffffffu, M, off));

    // predicated prefetch: all of this warp's slot partials in flight at once
    const float4* pp = (const float4*)(g_po + ((size_t)b * MAXSLOT * HH + h) * DD) + lane;
    float4 v[NPF];
    float  em[NPF], el[NPF];
    #pragma unroll
    for (int i = 0; i < NPF; i++) {
        const int s = warp + i * 8;
        if (s < ns) {
            v[i]  = pp[(size_t)s * (HH * DD / 4)];
            em[i] = sm[s];
            el[i] = sl[s];
        }
    }

    float L = 0.f;
    float4 o = make_float4(0.f, 0.f, 0.f, 0.f);
    #pragma unroll
    for (int i = 0; i < NPF; i++) {
        const int s = warp + i * 8;
        if (s < ns) {
            float e = __expf(em[i] - M);
            L += e * el[i];
            o.x += e * v[i].x; o.y += e * v[i].y;
            o.z += e * v[i].z; o.w += e * v[i].w;
        }
    }
    pO[warp][lane] = o;
    if (lane == 0) pL[warp] = L;
    __syncthreads();

    if (warp == 0) {
        float Lt = 0.f;
        float4 ot = make_float4(0.f, 0.f, 0.f, 0.f);
        #pragma unroll
        for (int i = 0; i < 8; i++) {
            Lt += pL[i];
            float4 t = pO[i][lane];
            ot.x += t.x; ot.y += t.y; ot.z += t.z; ot.w += t.w;
        }
        float inv = 1.0f / Lt;
        float4 r = make_float4(ot.x * inv, ot.y * inv, ot.z * inv, ot.w * inv);
        *((float4*)(out + (size_t)bh * DD) + lane) = r;
    }
}

extern "C" void kernel_launch(void* const* d_in, const int* in_sizes, int n_in,
                              void* d_out, int out_size) {
    const float* qkv = (const float*)d_in[0];
    const float* kc  = (const float*)d_in[1];
    const float* vc  = (const float*)d_in[2];
    const int* plen  = (const int*)d_in[3];
    const int* playr = (const int*)d_in[4];
    float* out = (float*)d_out;

    int Scap = in_sizes[1] / (BB * NLL * HH * DD);

    attn_batch_k<<<NCTA, 256>>>(qkv, kc, vc, plen, playr, Scap);
    reduce5_k<<<BB * HH, 256>>>(out, plen);
}